// round 12
// baseline (speedup 1.0000x reference)
#include <cuda_runtime.h>
#include <cuda_fp16.h>
#include <cstdint>

// out = relu(x @ W_w^T + W_b)   (attention collapses: softmax rows sum to 1).
//
// R12 = R10 (BK=32, fp16 single-product) with PREFETCH DISTANCE 2:
//   iter ch:  LDG chunk ch+2 -> P[ch%2]   (budget ~2 chunk bodies >> 600cyc)
//             compute chunk ch from smem ring stage (ch%3)
//             cvt+STS chunk ch+1 from P[(ch+1)%2] -> stage ((ch+1)%3)
//             __syncthreads()
//   3-stage smem ring (46 KB), two alternating register load buffers.
// R11 showed distance-1 leaves LDG latency exposed at the cvt step
// (issue 21%, all pipes idle). rel_err must stay bit-identical 2.944e-4.

#define D_DIM 256
#define BM 128
#define BN 64
#define BK 32
#define N_CHUNKS (D_DIM / BK)      // 8
#define ROWB 80                    // (32+8) fp16 row stride: conflict-free ldsm

#define OFF_A 0
#define OFF_B (BM * ROWB)                 // 10240
#define STAGE_BYTES (OFF_B + BN * ROWB)   // 15360
#define SMEM_TOTAL (3 * STAGE_BYTES)      // 46080

__device__ __forceinline__ uint32_t smem_u32(const void* p) {
    uint32_t a;
    asm("{ .reg .u64 t; cvta.to.shared.u64 t, %1; cvt.u32.u64 %0, t; }" : "=r"(a) : "l"(p));
    return a;
}

__device__ __forceinline__ void ldsm_x4(uint32_t* r, uint32_t addr) {
    asm volatile("ldmatrix.sync.aligned.m8n8.x4.shared.b16 {%0,%1,%2,%3}, [%4];"
                 : "=r"(r[0]), "=r"(r[1]), "=r"(r[2]), "=r"(r[3]) : "r"(addr));
}

__device__ __forceinline__ void mma_f16(float* d, const uint32_t* a, const uint32_t* b) {
    asm volatile("mma.sync.aligned.m16n8k16.row.col.f32.f16.f16.f32 "
                 "{%0,%1,%2,%3}, {%4,%5,%6,%7}, {%8,%9}, {%0,%1,%2,%3};"
                 : "+f"(d[0]), "+f"(d[1]), "+f"(d[2]), "+f"(d[3])
                 : "r"(a[0]), "r"(a[1]), "r"(a[2]), "r"(a[3]),
                   "r"(b[0]), "r"(b[1]));
}

// float4 -> fp16x4, one 8 B store.
__device__ __forceinline__ void cvt_store(uint32_t addr, float4 v) {
    __half2 h0 = __floats2half2_rn(v.x, v.y);
    __half2 h1 = __floats2half2_rn(v.z, v.w);
    uint32_t h0u = *(uint32_t*)&h0, h1u = *(uint32_t*)&h1;
    asm volatile("st.shared.v2.b32 [%0], {%1, %2};" :: "r"(addr), "r"(h0u), "r"(h1u) : "memory");
}

__global__ __launch_bounds__(256, 2)
void fcgat_hmma(const float* __restrict__ A,     // x  [32768, 256]
                const float* __restrict__ W,     // W  [256, 256]
                const float* __restrict__ bias,  // [256]
                float* __restrict__ C)           // [32768, 256]
{
    extern __shared__ __align__(16) unsigned char smem[];
    const uint32_t sb = smem_u32(smem);

    const int t   = threadIdx.x;
    const int l   = t & 31;
    const int wid = t >> 5;
    const int wm  = wid & 3;          // 4 warps along M
    const int wn  = wid >> 2;         // 2 warps along N
    const int m0  = wm * 32;
    const int n0  = wn * 32;

    const float* Ag = A + (size_t)blockIdx.y * BM * D_DIM;
    const float* Bg = W + (size_t)blockIdx.x * BN * D_DIM;

    // Per-thread load/store coordinates (fixed): A 4 float4, B 2 float4.
    const int ar[4] = { (t + 0*256) >> 3, (t + 1*256) >> 3, (t + 2*256) >> 3, (t + 3*256) >> 3 };
    const int ac    = (t & 7) * 4;
    const uint32_t aso[4] = {
        (uint32_t)(ar[0] * ROWB + (t & 7) * 8), (uint32_t)(ar[1] * ROWB + (t & 7) * 8),
        (uint32_t)(ar[2] * ROWB + (t & 7) * 8), (uint32_t)(ar[3] * ROWB + (t & 7) * 8) };

    float acc[2][4][4];
    #pragma unroll
    for (int i = 0; i < 2; i++)
        #pragma unroll
        for (int j = 0; j < 4; j++)
            #pragma unroll
            for (int c = 0; c < 4; c++)
                acc[i][j][c] = 0.0f;

    const uint32_t a_lane = (uint32_t)((m0 + (l & 15)) * ROWB + (l >> 4) * 16);
    const uint32_t b_lane = (uint32_t)((n0 + (l & 7) + ((l >> 4) << 3)) * ROWB
                                       + ((l >> 3) & 1) * 16);

    float4 p0a[4], p1a[4];
    float4 p0b[2], p1b[2];

    #define LDG_CHUNK(PA, PB, kc_) do {                                            \
        _Pragma("unroll")                                                          \
        for (int i_ = 0; i_ < 4; i_++)                                             \
            (PA)[i_] = *(const float4*)(Ag + (size_t)ar[i_] * D_DIM + (kc_) + ac); \
        _Pragma("unroll")                                                          \
        for (int i_ = 0; i_ < 2; i_++)                                             \
            (PB)[i_] = *(const float4*)(Bg + (size_t)ar[i_] * D_DIM + (kc_) + ac); \
    } while (0)

    #define STS_CHUNK(PA, PB, sbase_) do {                                         \
        _Pragma("unroll")                                                          \
        for (int i_ = 0; i_ < 4; i_++)                                             \
            cvt_store((sbase_) + OFF_A + aso[i_], (PA)[i_]);                       \
        _Pragma("unroll")                                                          \
        for (int i_ = 0; i_ < 2; i_++)                                             \
            cvt_store((sbase_) + OFF_B + aso[i_], (PB)[i_]);                       \
    } while (0)

    #define COMPUTE_CHUNK(sbase_) do {                                             \
        _Pragma("unroll")                                                          \
        for (int ks_ = 0; ks_ < 2; ks_++) {                                        \
            const uint32_t ko_ = (uint32_t)(ks_ * 32);                             \
            uint32_t ah_[2][4], bh_[2][4];                                         \
            _Pragma("unroll")                                                      \
            for (int i_ = 0; i_ < 2; i_++)                                         \
                ldsm_x4(ah_[i_], (sbase_) + OFF_A + a_lane + ko_ + i_ * 16 * ROWB);\
            _Pragma("unroll")                                                      \
            for (int jp_ = 0; jp_ < 2; jp_++)                                      \
                ldsm_x4(bh_[jp_], (sbase_) + OFF_B + b_lane + ko_ + jp_ * 16 * ROWB);\
            _Pragma("unroll")                                                      \
            for (int i_ = 0; i_ < 2; i_++)                                         \
                _Pragma("unroll")                                                  \
                for (int j_ = 0; j_ < 4; j_++)                                     \
                    mma_f16(acc[i_][j_], ah_[i_], bh_[j_ >> 1] + (j_ & 1) * 2);    \
        }                                                                          \
    } while (0)

    // ---- prologue: chunks 0 and 1 in flight; stage chunk 0 ----
    LDG_CHUNK(p0a, p0b, 0);
    LDG_CHUNK(p1a, p1b, BK);
    STS_CHUNK(p0a, p0b, sb + 0 * STAGE_BYTES);
    __syncthreads();

    // ring bases: cur = compute stage, nxt = stage being filled, fre = spare
    uint32_t s_cur = sb;
    uint32_t s_nxt = sb + STAGE_BYTES;
    uint32_t s_fre = sb + 2 * STAGE_BYTES;

    #pragma unroll
    for (int ch = 0; ch < N_CHUNKS; ch++) {
        // (1) LDG chunk ch+2 into the buffer freed last iteration
        if (ch + 2 < N_CHUNKS) {
            if ((ch & 1) == 0) LDG_CHUNK(p0a, p0b, (ch + 2) * BK);
            else               LDG_CHUNK(p1a, p1b, (ch + 2) * BK);
        }

        // (2) compute chunk ch
        COMPUTE_CHUNK(s_cur);

        // (3) cvt+STS chunk ch+1 into s_nxt
        if (ch + 1 < N_CHUNKS) {
            if ((ch & 1) == 0) STS_CHUNK(p1a, p1b, s_nxt);
            else               STS_CHUNK(p0a, p0b, s_nxt);
        }

        // (4) barrier + rotate ring
        __syncthreads();
        uint32_t tmp = s_cur;
        s_cur = s_nxt; s_nxt = s_fre; s_fre = tmp;
    }

    // ---- epilogue: bias + relu ----
    const int g  = l >> 2;
    const int tc = l & 3;
    #pragma unroll
    for (int i = 0; i < 2; i++) {
        const size_t r0 = (size_t)blockIdx.y * BM + m0 + 16 * i + g;
        const size_t r1 = r0 + 8;
        #pragma unroll
        for (int j = 0; j < 4; j++) {
            const int col = blockIdx.x * BN + n0 + 8 * j + 2 * tc;
            float2 bv = *(const float2*)(bias + col);
            float2 o0, o1;
            o0.x = fmaxf(acc[i][j][0] + bv.x, 0.0f);
            o0.y = fmaxf(acc[i][j][1] + bv.y, 0.0f);
            o1.x = fmaxf(acc[i][j][2] + bv.x, 0.0f);
            o1.y = fmaxf(acc[i][j][3] + bv.y, 0.0f);
            *(float2*)(C + r0 * D_DIM + col) = o0;
            *(float2*)(C + r1 * D_DIM + col) = o1;
        }
    }
}

extern "C" void kernel_launch(void* const* d_in, const int* in_sizes, int n_in,
                              void* d_out, int out_size)
{
    const float* x   = (const float*)d_in[0];
    const float* W_w = (const float*)d_in[1];
    const float* W_b = (const float*)d_in[2];
    float* out = (float*)d_out;

    int M = in_sizes[0] / D_DIM;                  // 32768
    cudaFuncSetAttribute(fcgat_hmma,
                         cudaFuncAttributeMaxDynamicSharedMemorySize, SMEM_TOTAL);
    dim3 grid(D_DIM / BN, M / BM);                // (4, 256) = 1024 CTAs
    fcgat_hmma<<<grid, 256, SMEM_TOTAL>>>(x, W_w, W_b, out);
}

// round 13
// speedup vs baseline: 1.0494x; 1.0494x over previous
#include <cuda_runtime.h>
#include <cuda_fp16.h>
#include <cstdint>

// out = relu(x @ W_w^T + W_b)   (attention collapses: softmax rows sum to 1).
//
// R13: delete the LDG->reg->cvt->STS staging path (shown invariant-bound in
// R10-R12). A is fed by cp.async.cg (LDGSTS) into a 3-stage fp32 smem ring —
// no registers, no scoreboard dependency in compute. Warps LDS fp32 fragments
// and convert to fp16 in-register. B is converted to fp16 smem once at the
// prologue (loop-invariant). Mainloop: wait_group+sync, ldsm B, 16 MMAs,
// issue chunk ch+2. rel_err must stay bit-identical 2.944e-4.

#define D_DIM 256
#define BM 128
#define BN 64
#define BK 32
#define N_CHUNKS (D_DIM / BK)      // 8
#define N_STAGES 3

#define ROWB_AF 160                // fp32 A row stride bytes (32 floats + 8 pad)
#define A_STAGE (BM * ROWB_AF)     // 20480
#define OFF_B (N_STAGES * A_STAGE) // 61440
#define ROWB_B 528                 // fp16 B row stride (256+8 halves)
#define SMEM_TOTAL (OFF_B + BN * ROWB_B)   // 95232

__device__ __forceinline__ uint32_t smem_u32(const void* p) {
    uint32_t a;
    asm("{ .reg .u64 t; cvta.to.shared.u64 t, %1; cvt.u32.u64 %0, t; }" : "=r"(a) : "l"(p));
    return a;
}

__device__ __forceinline__ void cp_async16(uint32_t dst, const void* src) {
    asm volatile("cp.async.cg.shared.global [%0], [%1], 16;"
                 :: "r"(dst), "l"(src) : "memory");
}
#define CP_COMMIT() asm volatile("cp.async.commit_group;" ::: "memory")
#define CP_WAIT(n)  asm volatile("cp.async.wait_group %0;" :: "n"(n) : "memory")

__device__ __forceinline__ void ldsm_x4(uint32_t* r, uint32_t addr) {
    asm volatile("ldmatrix.sync.aligned.m8n8.x4.shared.b16 {%0,%1,%2,%3}, [%4];"
                 : "=r"(r[0]), "=r"(r[1]), "=r"(r[2]), "=r"(r[3]) : "r"(addr));
}

__device__ __forceinline__ void mma_f16(float* d, const uint32_t* a, const uint32_t* b) {
    asm volatile("mma.sync.aligned.m16n8k16.row.col.f32.f16.f16.f32 "
                 "{%0,%1,%2,%3}, {%4,%5,%6,%7}, {%8,%9}, {%0,%1,%2,%3};"
                 : "+f"(d[0]), "+f"(d[1]), "+f"(d[2]), "+f"(d[3])
                 : "r"(a[0]), "r"(a[1]), "r"(a[2]), "r"(a[3]),
                   "r"(b[0]), "r"(b[1]));
}

__device__ __forceinline__ uint32_t lds_cvt(uint32_t addr) {
    float x, y;
    asm volatile("ld.shared.v2.f32 {%0,%1}, [%2];" : "=f"(x), "=f"(y) : "r"(addr));
    __half2 h = __floats2half2_rn(x, y);
    return *(uint32_t*)&h;
}

// float4 -> fp16x4, one 8 B store (B prologue only).
__device__ __forceinline__ void cvt_store(uint32_t addr, float4 v) {
    __half2 h0 = __floats2half2_rn(v.x, v.y);
    __half2 h1 = __floats2half2_rn(v.z, v.w);
    uint32_t h0u = *(uint32_t*)&h0, h1u = *(uint32_t*)&h1;
    asm volatile("st.shared.v2.b32 [%0], {%1, %2};" :: "r"(addr), "r"(h0u), "r"(h1u) : "memory");
}

__global__ __launch_bounds__(256, 2)
void fcgat_hmma(const float* __restrict__ A,     // x  [32768, 256]
                const float* __restrict__ W,     // W  [256, 256]
                const float* __restrict__ bias,  // [256]
                float* __restrict__ C)           // [32768, 256]
{
    extern __shared__ __align__(16) unsigned char smem[];
    const uint32_t sb = smem_u32(smem);

    const int t   = threadIdx.x;
    const int l   = t & 31;
    const int wid = t >> 5;
    const int wm  = wid & 3;          // 4 warps along M
    const int wn  = wid >> 2;         // 2 warps along N
    const int m0  = wm * 32;
    const int n0  = wn * 32;

    const float* Ag = A + (size_t)blockIdx.y * BM * D_DIM;
    const float* Bg = W + (size_t)blockIdx.x * BN * D_DIM;

    // cp.async coordinates: 1024 16B segments (128 rows x 8 segs) -> 4/thread
    const int seg_row[4] = { (t + 0*256) >> 3, (t + 1*256) >> 3,
                             (t + 2*256) >> 3, (t + 3*256) >> 3 };
    const int seg_col = (t & 7) * 4;          // float offset of this 16B seg in row

    #define ISSUE_CHUNK(ch_) do {                                                  \
        const uint32_t st_ = sb + ((ch_) % N_STAGES) * A_STAGE;                    \
        const int kc_ = (ch_) * BK;                                                \
        _Pragma("unroll")                                                          \
        for (int i_ = 0; i_ < 4; i_++)                                             \
            cp_async16(st_ + (uint32_t)(seg_row[i_] * ROWB_AF + seg_col * 4),      \
                       Ag + (size_t)seg_row[i_] * D_DIM + kc_ + seg_col);          \
        CP_COMMIT();                                                               \
    } while (0)

    // ---- prologue: issue chunks 0,1; convert B to fp16 smem ----
    ISSUE_CHUNK(0);
    ISSUE_CHUNK(1);
    {
        // B: 64 rows x 64 float4 = 4096 -> 16/thread
        #pragma unroll
        for (int i = 0; i < 16; i++) {
            int idx = t + i * 256;
            int row = idx >> 6;
            int c4  = idx & 63;
            float4 v = *(const float4*)(Bg + (size_t)row * D_DIM + c4 * 4);
            cvt_store(sb + OFF_B + (uint32_t)(row * ROWB_B + c4 * 8), v);
        }
    }

    float acc[2][4][4];
    #pragma unroll
    for (int i = 0; i < 2; i++)
        #pragma unroll
        for (int j = 0; j < 4; j++)
            #pragma unroll
            for (int c = 0; c < 4; c++)
                acc[i][j][c] = 0.0f;

    // A fragment LDS base: row = m0 + (l>>2), float-pair col = (l&3)*2
    const uint32_t a_frag = (uint32_t)((m0 + (l >> 2)) * ROWB_AF + (l & 3) * 8);
    const uint32_t b_lane = (uint32_t)((n0 + (l & 7) + ((l >> 4) << 3)) * ROWB_B
                                       + ((l >> 3) & 1) * 16);

    for (int ch = 0; ch < N_CHUNKS; ch++) {
        // (1) wait for chunk ch's cp.async group
        if (ch + 1 < N_CHUNKS) CP_WAIT(1);
        else                   CP_WAIT(0);
        // (2) barrier: stage ch visible to all warps; all warps done reading
        //     stage (ch-1)%3 -> safe to overwrite it with chunk ch+2 below
        __syncthreads();
        // (3) issue chunk ch+2 into stage (ch+2)%3 == (ch-1)%3
        if (ch + 2 < N_CHUNKS) ISSUE_CHUNK(ch + 2);

        // (4) compute chunk ch
        const uint32_t abase = sb + (ch % N_STAGES) * A_STAGE + a_frag;
        #pragma unroll
        for (int ks = 0; ks < 2; ks++) {
            // A fragments: LDS fp32 + in-register cvt to fp16
            uint32_t ah[2][4];
            #pragma unroll
            for (int i = 0; i < 2; i++) {
                const uint32_t fa = abase + (uint32_t)(i * 16 * ROWB_AF + ks * 64);
                ah[i][0] = lds_cvt(fa);
                ah[i][1] = lds_cvt(fa + 8 * ROWB_AF);
                ah[i][2] = lds_cvt(fa + 32);
                ah[i][3] = lds_cvt(fa + 8 * ROWB_AF + 32);
            }
            // B fragments from persistent fp16 smem
            uint32_t bh[2][4];
            const uint32_t koB = (uint32_t)(ch * 64 + ks * 32);
            #pragma unroll
            for (int jp = 0; jp < 2; jp++)
                ldsm_x4(bh[jp], sb + OFF_B + b_lane + koB + jp * 16 * ROWB_B);

            #pragma unroll
            for (int i = 0; i < 2; i++)
                #pragma unroll
                for (int j = 0; j < 4; j++)
                    mma_f16(acc[i][j], ah[i], bh[j >> 1] + (j & 1) * 2);
        }
    }

    // ---- epilogue: bias + relu ----
    const int g  = l >> 2;
    const int tc = l & 3;
    #pragma unroll
    for (int i = 0; i < 2; i++) {
        const size_t r0 = (size_t)blockIdx.y * BM + m0 + 16 * i + g;
        const size_t r1 = r0 + 8;
        #pragma unroll
        for (int j = 0; j < 4; j++) {
            const int col = blockIdx.x * BN + n0 + 8 * j + 2 * tc;
            float2 bv = *(const float2*)(bias + col);
            float2 o0, o1;
            o0.x = fmaxf(acc[i][j][0] + bv.x, 0.0f);
            o0.y = fmaxf(acc[i][j][1] + bv.y, 0.0f);
            o1.x = fmaxf(acc[i][j][2] + bv.x, 0.0f);
            o1.y = fmaxf(acc[i][j][3] + bv.y, 0.0f);
            *(float2*)(C + r0 * D_DIM + col) = o0;
            *(float2*)(C + r1 * D_DIM + col) = o1;
        }
    }
}

extern "C" void kernel_launch(void* const* d_in, const int* in_sizes, int n_in,
                              void* d_out, int out_size)
{
    const float* x   = (const float*)d_in[0];
    const float* W_w = (const float*)d_in[1];
    const float* W_b = (const float*)d_in[2];
    float* out = (float*)d_out;

    int M = in_sizes[0] / D_DIM;                  // 32768
    cudaFuncSetAttribute(fcgat_hmma,
                         cudaFuncAttributeMaxDynamicSharedMemorySize, SMEM_TOTAL);
    dim3 grid(D_DIM / BN, M / BM);                // (4, 256) = 1024 CTAs
    fcgat_hmma<<<grid, 256, SMEM_TOTAL>>>(x, W_w, W_b, out);
}